// round 15
// baseline (speedup 1.0000x reference)
#include <cuda_runtime.h>
#include <cuda_fp16.h>
#include <math.h>
#include <stdint.h>

#define B_    32
#define SXX   2048
#define SYY   2048
#define DD    160
#define BM    128
#define BN    32
#define NT    (SYY / BN)
#define ROWB  336          // padded row pitch in bytes (168 f16)

// hi/lo f16 projections (natural [b][m][d] layout)
__device__ __half g_qhi[(size_t)B_ * SXX * DD];
__device__ __half g_qlo[(size_t)B_ * SXX * DD];
__device__ __half g_khi[(size_t)B_ * SYY * DD];
__device__ __half g_klo[(size_t)B_ * SYY * DD];
__device__ __half g_vhi[(size_t)B_ * SYY * DD];

// ---------------------------------------------------------------------------
// low-level helpers
// ---------------------------------------------------------------------------
__device__ __forceinline__ uint32_t smem_u32(const void* p) {
    uint32_t r;
    asm("{ .reg .u64 t; cvta.to.shared.u64 t, %1; cvt.u32.u64 %0, t; }"
        : "=r"(r) : "l"(p));
    return r;
}
__device__ __forceinline__ void cp16(uint32_t s, const void* g) {
    asm volatile("cp.async.cg.shared.global [%0], [%1], 16;" :: "r"(s), "l"(g));
}
__device__ __forceinline__ void cp_commit() {
    asm volatile("cp.async.commit_group;" ::: "memory");
}
__device__ __forceinline__ void cp_wait_all() {
    asm volatile("cp.async.wait_group 0;" ::: "memory");
}
__device__ __forceinline__ void ldsm4(uint32_t* r, uint32_t a) {
    asm volatile("ldmatrix.sync.aligned.m8n8.x4.shared.b16 {%0,%1,%2,%3}, [%4];"
                 : "=r"(r[0]), "=r"(r[1]), "=r"(r[2]), "=r"(r[3]) : "r"(a));
}
__device__ __forceinline__ void ldsm4t(uint32_t* r, uint32_t a) {
    asm volatile("ldmatrix.sync.aligned.m8n8.x4.trans.shared.b16 {%0,%1,%2,%3}, [%4];"
                 : "=r"(r[0]), "=r"(r[1]), "=r"(r[2]), "=r"(r[3]) : "r"(a));
}
__device__ __forceinline__ void ldsm2t(uint32_t* r, uint32_t a) {
    asm volatile("ldmatrix.sync.aligned.m8n8.x2.trans.shared.b16 {%0,%1}, [%2];"
                 : "=r"(r[0]), "=r"(r[1]) : "r"(a));
}
__device__ __forceinline__ void mma_f16(float* c, const uint32_t* a,
                                        uint32_t b0, uint32_t b1) {
    asm volatile("mma.sync.aligned.m16n8k16.row.col.f32.f16.f16.f32 "
                 "{%0,%1,%2,%3}, {%4,%5,%6,%7}, {%8,%9}, {%0,%1,%2,%3};"
                 : "+f"(c[0]), "+f"(c[1]), "+f"(c[2]), "+f"(c[3])
                 : "r"(a[0]), "r"(a[1]), "r"(a[2]), "r"(a[3]), "r"(b0), "r"(b1));
}
__device__ __forceinline__ float ex2f(float x) {
    float r;
    asm("ex2.approx.ftz.f32 %0, %1;" : "=f"(r) : "f"(x));
    return r;
}
__device__ __forceinline__ uint32_t ex2h2(uint32_t x) {
    uint32_t r;
    asm("ex2.approx.f16x2 %0, %1;" : "=r"(r) : "r"(x));
    return r;
}
__device__ __forceinline__ uint32_t packh(float a, float b) {
    __half2 t = __floats2half2_rn(a, b);
    return *reinterpret_cast<uint32_t*>(&t);
}
// fp32x4 -> hi/lo f16x2 pairs
__device__ __forceinline__ void cvt_hilo(float4 v, uint2& hp, uint2& lp) {
    __half h0 = __float2half_rn(v.x);
    __half h1 = __float2half_rn(v.y);
    __half h2 = __float2half_rn(v.z);
    __half h3 = __float2half_rn(v.w);
    hp.x = ((uint32_t)__half_as_ushort(h1) << 16) | __half_as_ushort(h0);
    hp.y = ((uint32_t)__half_as_ushort(h3) << 16) | __half_as_ushort(h2);
    lp.x = packh(v.x - __half2float(h0), v.y - __half2float(h1));
    lp.y = packh(v.z - __half2float(h2), v.w - __half2float(h3));
}

// ---------------------------------------------------------------------------
// Merged tensor-core projections with FUSED fp32->f16 hi/lo conversion.
// (unchanged from R12/R14)
// ---------------------------------------------------------------------------
#define PSAH 0
#define PSAL 43008
#define PSWH 86016
#define PSWL 139776
#define PROJ_SMEM 193536

__global__ __launch_bounds__(256, 1) void proj_mma(
    const float* __restrict__ x, const float* __restrict__ y,
    const float* __restrict__ wq, const float* __restrict__ wk,
    const float* __restrict__ wv,
    const float* __restrict__ bq, const float* __restrict__ bk,
    const float* __restrict__ bv,
    __half* __restrict__ qh, __half* __restrict__ ql,
    __half* __restrict__ kh, __half* __restrict__ kl,
    __half* __restrict__ vh)
{
    extern __shared__ char smem[];
    const uint32_t sb = smem_u32(smem);
    const int tid  = threadIdx.x;
    const int lane = tid & 31;
    const int w    = tid >> 5;
    const size_t m0 = (size_t)blockIdx.x * BM;

    const float *Asrc, *Wsrc, *bias;
    __half *Chi, *Clo;
    float ascale = 1.0f;
    if (blockIdx.y == 0) {
        Asrc = x; Wsrc = wq; bias = bq;
        Chi = qh; Clo = ql; ascale = 1.4426950408889634f;   // log2(e)
    } else if (blockIdx.y == 1) {
        Asrc = y; Wsrc = wk; bias = bk;
        Chi = kh; Clo = kl;
    } else {
        Asrc = y; Wsrc = wv; bias = bv;
        Chi = vh; Clo = nullptr;
    }

#pragma unroll
    for (int i = 0; i < 20; i++) {
        int idx = i * 256 + tid;
        int row = idx / 40, c4 = idx % 40;
        float4 v = *(const float4*)(Asrc + (m0 + row) * DD + c4 * 4);
        uint2 hp, lp;
        cvt_hilo(v, hp, lp);
        *(uint2*)(smem + PSAH + row * ROWB + c4 * 8) = hp;
        *(uint2*)(smem + PSAL + row * ROWB + c4 * 8) = lp;
    }
#pragma unroll
    for (int i = 0; i < 25; i++) {
        int idx = i * 256 + tid;
        int row = idx / 40, c4 = idx % 40;
        float4 v = *(const float4*)(Wsrc + (size_t)row * DD + c4 * 4);
        uint2 hp, lp;
        cvt_hilo(v, hp, lp);
        *(uint2*)(smem + PSWH + row * ROWB + c4 * 8) = hp;
        *(uint2*)(smem + PSWL + row * ROWB + c4 * 8) = lp;
    }
    __syncthreads();

    const uint32_t aOff = (uint32_t)((16 * w + (lane & 15)) * ROWB
                                     + ((lane >> 4) << 4));
    const uint32_t bOff = (uint32_t)(((lane & 7) + ((lane >> 4) << 3)) * ROWB
                                     + (((lane >> 3) & 1) << 4));

    float c[20][4];
#pragma unroll
    for (int j = 0; j < 20; j++)
#pragma unroll
        for (int u = 0; u < 4; u++) c[j][u] = 0.f;

#pragma unroll
    for (int ks = 0; ks < 10; ks++) {
        uint32_t ah[4], al[4];
        ldsm4(ah, sb + PSAH + aOff + ks * 32);
        ldsm4(al, sb + PSAL + aOff + ks * 32);
#pragma unroll
        for (int nb = 0; nb < 10; nb++) {
            uint32_t bh[4], bl[4];
            ldsm4(bh, sb + PSWH + bOff + nb * (16 * ROWB) + ks * 32);
            ldsm4(bl, sb + PSWL + bOff + nb * (16 * ROWB) + ks * 32);
            mma_f16(c[2 * nb],     ah, bh[0], bh[1]);
            mma_f16(c[2 * nb + 1], ah, bh[2], bh[3]);
            mma_f16(c[2 * nb],     ah, bl[0], bl[1]);
            mma_f16(c[2 * nb + 1], ah, bl[2], bl[3]);
            mma_f16(c[2 * nb],     al, bh[0], bh[1]);
            mma_f16(c[2 * nb + 1], al, bh[2], bh[3]);
        }
    }

    const size_t r0 = m0 + 16 * w + (lane >> 2);
    const int cb = 2 * (lane & 3);
#pragma unroll
    for (int j = 0; j < 20; j++) {
        int n = 8 * j + cb;
        float2 bvv = *(const float2*)(bias + n);
        float v0 = (c[j][0] + bvv.x) * ascale, v1 = (c[j][1] + bvv.y) * ascale;
        float v2 = (c[j][2] + bvv.x) * ascale, v3 = (c[j][3] + bvv.y) * ascale;
        __half h0 = __float2half_rn(v0);
        __half h1 = __float2half_rn(v1);
        __half h2 = __float2half_rn(v2);
        __half h3 = __float2half_rn(v3);
        *(uint32_t*)(Chi + r0 * DD + n) =
            ((uint32_t)__half_as_ushort(h1) << 16) | __half_as_ushort(h0);
        *(uint32_t*)(Chi + (r0 + 8) * DD + n) =
            ((uint32_t)__half_as_ushort(h3) << 16) | __half_as_ushort(h2);
        if (Clo) {
            *(uint32_t*)(Clo + r0 * DD + n) =
                packh(v0 - __half2float(h0), v1 - __half2float(h1));
            *(uint32_t*)(Clo + (r0 + 8) * DD + n) =
                packh(v2 - __half2float(h2), v3 - __half2float(h3));
        }
    }
}

// ---------------------------------------------------------------------------
// f16 HMMA flash attention — PING-PONG: two independent 128-thread groups,
// each owns 64 query rows x full KV (BN=32), own K/V rings, own named
// barrier. Groups interleave on the SMSPs: one group's softmax overlaps the
// other group's MMAs. Q-hi frags in registers, Q-lo permanent in smem.
// SMEM: Qlo @0 (43008, 128 rows)
//   K rings: g0 @43008 (+21504 for buf1), g1 @86016 (+21504)
//            each K buf: Kh +0 (10752), Kl +10752
//   V rings: g0 @129024 (3 x 10752), g1 @161280 (3 x 10752)
// ---------------------------------------------------------------------------
#define SQLO  0
#define KLOFF 10752
#define SMEM_TOTAL 193536

__global__ __launch_bounds__(256, 1) void attn_kernel(
    const __half* __restrict__ qhi, const __half* __restrict__ qlo,
    const __half* __restrict__ khi, const __half* __restrict__ klo,
    const __half* __restrict__ vhi,
    const float* __restrict__ gx, float* __restrict__ gout)
{
    extern __shared__ char smem[];
    const uint32_t sb = smem_u32(smem);
    const int tid  = threadIdx.x;
    const int lane = tid & 31;
    const int g    = tid >> 7;          // group 0 / 1
    const int wg   = (tid >> 5) & 3;    // warp within group
    const int lt   = tid & 127;         // thread within group
    const int b    = blockIdx.y;
    const int m0   = blockIdx.x * BM;

    const uint32_t kbase = 43008u + 43008u * (uint32_t)g;
    const uint32_t vbase = 129024u + 32256u * (uint32_t)g;

    // ---- stage Q: lo -> permanent @0, hi -> temp @43008 (both groups') ----
    {
        const size_t qrow = ((size_t)b * SXX + m0);
#pragma unroll
        for (int i = 0; i < 20; i++) {
            int idx  = i * 256 + tid;
            int half = idx / 2560;          // 0: hi (temp), 1: lo (permanent)
            int rem  = idx - half * 2560;
            int row  = rem / 20, cc = rem - row * 20;
            cp16(sb + (half ? SQLO : 43008u) + row * ROWB + cc * 16,
                 (half ? qlo : qhi) + (qrow + row) * DD + cc * 8);
        }
    }
    cp_commit();
    cp_wait_all();
    __syncthreads();

    // ---- Q-hi a-frags -> registers; rows = 64g + 16wg + (lane&15) ----
    const uint32_t qOff = (uint32_t)((64 * g + 16 * wg + (lane & 15)) * ROWB
                                     + ((lane >> 4) << 4));
    uint32_t qh_f[10][4];
#pragma unroll
    for (int ks = 0; ks < 10; ks++)
        ldsm4(qh_f[ks], sb + 43008u + qOff + ks * 32);
    __syncthreads();   // Q-hi temp reads done; region now owned by K rings

    // ---- init V pad cols 160-167 of all 6 V buffers: {1,0,...,0} ----
    if (tid < 192) {
        int bufi = tid >> 5, row = tid & 31;   // 6 bufs x 32 rows
        int gg = bufi / 3, bb = bufi % 3;
        uint4* p = (uint4*)(smem + 129024 + gg * 32256 + bb * 10752
                            + row * ROWB + 320);
        *p = make_uint4(0x00003C00u, 0u, 0u, 0u);   // half 1.0 at col 160
    }

    const __half* gk0 = khi + (size_t)b * SYY * DD;
    const __half* gk1 = klo + (size_t)b * SYY * DD;
    const __half* gv  = vhi + (size_t)b * SYY * DD;

    // ---- tile 0 load (group-local: 1920 cp16 over 128 threads) ----
#pragma unroll
    for (int i = 0; i < 15; i++) {
        int idx = i * 128 + lt;
        int mat = idx / 640;
        int rem = idx - mat * 640;
        int row = rem / 20, cc = rem - row * 20;
        const __half* gsrc = (mat == 0) ? gk0 : (mat == 1) ? gk1 : gv;
        uint32_t dst = (mat == 2) ? vbase : kbase + mat * KLOFF;
        cp16(sb + dst + row * ROWB + cc * 16, gsrc + (size_t)row * DD + cc * 8);
    }
    cp_commit();
    cp_wait_all();
    __syncthreads();   // full CTA: covers cross-group V-pad init too

    const uint32_t kOff = (uint32_t)(((lane & 7) + ((lane >> 4) << 3)) * ROWB
                                     + (((lane >> 3) & 1) << 4));
    const uint32_t vOff = (uint32_t)(((lane & 7) + (((lane >> 3) & 1) << 3)) * ROWB
                                     + ((lane >> 4) << 4));
    const uint32_t vOff2 = (uint32_t)(((lane & 7) + (((lane >> 3) & 1) << 3)) * ROWB);

    float o[21][4];   // blocks 0..19 = O cols 0..159; block 20 = l (col 160)
#pragma unroll
    for (int j = 0; j < 21; j++)
#pragma unroll
        for (int u = 0; u < 4; u++) o[j][u] = 0.f;

    float mh01 = -INFINITY, mh23 = -INFINITY;
    uint32_t pah[2][4];
    const int bar = g + 1;   // named barrier per group

    for (int t = 0; t < NT; t++) {
        const uint32_t kb  = sb + kbase + (uint32_t)(t & 1) * 21504u;
        const uint32_t pvb = sb + vbase + (uint32_t)((t + 2) % 3) * 10752u;

        if (t + 1 < NT) {
            const uint32_t nkb = sb + kbase + (uint32_t)((t + 1) & 1) * 21504u;
            const uint32_t nvb = sb + vbase + (uint32_t)((t + 1) % 3) * 10752u;
            const size_t grow = (size_t)(t + 1) * BN;
#pragma unroll
            for (int i = 0; i < 15; i++) {
                int idx = i * 128 + lt;
                int mat = idx / 640;
                int rem = idx - mat * 640;
                int row = rem / 20, cc = rem - row * 20;
                const __half* gsrc = (mat == 0) ? gk0 : (mat == 1) ? gk1 : gv;
                uint32_t dst = (mat == 2) ? nvb : nkb + (uint32_t)mat * KLOFF;
                cp16(dst + row * ROWB + cc * 16,
                     gsrc + (grow + row) * DD + cc * 8);
            }
            cp_commit();
        }

        // ---- S(t) = Q K^T : 3-term f16 hi/lo; Q-lo frags from smem ----
        float c[4][4];
#pragma unroll
        for (int j = 0; j < 4; j++)
#pragma unroll
            for (int u = 0; u < 4; u++) c[j][u] = 0.f;

#pragma unroll
        for (int ks = 0; ks < 10; ks++) {
            uint32_t qlf[4];
            ldsm4(qlf, sb + SQLO + qOff + ks * 32);
            uint32_t bh[8], bl[8];
            uint32_t kbb = kb + kOff + ks * 32;
            ldsm4(bh,     kbb);
            ldsm4(bh + 4, kbb + 16 * ROWB);
            ldsm4(bl,     kbb + KLOFF);
            ldsm4(bl + 4, kbb + KLOFF + 16 * ROWB);
#pragma unroll
            for (int j = 0; j < 4; j++) {
                mma_f16(c[j], qh_f[ks], bh[2 * j], bh[2 * j + 1]);
                mma_f16(c[j], qh_f[ks], bl[2 * j], bl[2 * j + 1]);
                mma_f16(c[j], qlf,      bh[2 * j], bh[2 * j + 1]);
            }
        }

        // ---- PV(t-1): 1-term (ph*vh) + ones column, k = 32 ----
        if (t > 0) {
#pragma unroll
            for (int ks = 0; ks < 2; ks++) {
#pragma unroll
                for (int jp = 0; jp < 10; jp++) {
                    uint32_t v4h[4];
                    ldsm4t(v4h, pvb + vOff + ks * (16 * ROWB) + jp * 32);
                    mma_f16(o[2 * jp],     pah[ks], v4h[0], v4h[1]);
                    mma_f16(o[2 * jp + 1], pah[ks], v4h[2], v4h[3]);
                }
                uint32_t v2[2];
                ldsm2t(v2, pvb + vOff2 + ks * (16 * ROWB) + 320);
                mma_f16(o[20], pah[ks], v2[0], v2[1]);
            }
        }

        // ---- online softmax(t): scores in log2 units; exp in f16x2 ----
        float mt01 = fmaxf(c[0][0], c[0][1]);
        float mt23 = fmaxf(c[0][2], c[0][3]);
#pragma unroll
        for (int j = 1; j < 4; j++) {
            mt01 = fmaxf(mt01, fmaxf(c[j][0], c[j][1]));
            mt23 = fmaxf(mt23, fmaxf(c[j][2], c[j][3]));
        }
        mt01 = fmaxf(mt01, __shfl_xor_sync(0xffffffffu, mt01, 1));
        mt01 = fmaxf(mt01, __shfl_xor_sync(0xffffffffu, mt01, 2));
        mt23 = fmaxf(mt23, __shfl_xor_sync(0xffffffffu, mt23, 1));
        mt23 = fmaxf(mt23, __shfl_xor_sync(0xffffffffu, mt23, 2));
        const bool upd = (mt01 > mh01) || (mt23 > mh23);
        float mn01 = fmaxf(mh01, mt01);
        float mn23 = fmaxf(mh23, mt23);
        float a01 = ex2f(mh01 - mn01);
        float a23 = ex2f(mh23 - mn23);
        mh01 = mn01; mh23 = mn23;

#pragma unroll
        for (int j = 0; j < 4; j++) {
            float t0 = c[j][0] - mn01;
            float t1 = c[j][1] - mn01;
            float t2 = c[j][2] - mn23;
            float t3 = c[j][3] - mn23;
            int ks = j >> 1, sl = (j & 1) << 1;
            pah[ks][sl]     = ex2h2(packh(t0, t1));
            pah[ks][sl + 1] = ex2h2(packh(t2, t3));
        }

        if (upd) {   // rescale O (incl. l column) only when max advanced
#pragma unroll
            for (int j = 0; j < 21; j++) {
                o[j][0] *= a01; o[j][1] *= a01;
                o[j][2] *= a23; o[j][3] *= a23;
            }
        }

        cp_wait_all();
        asm volatile("bar.sync %0, 128;" :: "r"(bar) : "memory");
    }

    // ---- final PV (tile NT-1) ----
    {
        const uint32_t pvb = sb + vbase + (uint32_t)((NT - 1) % 3) * 10752u;
#pragma unroll
        for (int ks = 0; ks < 2; ks++) {
#pragma unroll
            for (int jp = 0; jp < 10; jp++) {
                uint32_t v4h[4];
                ldsm4t(v4h, pvb + vOff + ks * (16 * ROWB) + jp * 32);
                mma_f16(o[2 * jp],     pah[ks], v4h[0], v4h[1]);
                mma_f16(o[2 * jp + 1], pah[ks], v4h[2], v4h[3]);
            }
            uint32_t v2[2];
            ldsm2t(v2, pvb + vOff2 + ks * (16 * ROWB) + 320);
            mma_f16(o[20], pah[ks], v2[0], v2[1]);
        }
    }

    // ---- epilogue: l = O col 160 (held by lanes with lane&3 == 0) ----
    const int srcl = lane & ~3;
    const float l01 = __shfl_sync(0xffffffffu, o[20][0], srcl);
    const float l23 = __shfl_sync(0xffffffffu, o[20][2], srcl);
    const float inv01 = 1.f / l01;
    const float inv23 = 1.f / l23;

    const int r0 = m0 + 64 * g + 16 * wg + (lane >> 2);
    const size_t row0 = ((size_t)b * SXX + r0) * DD;
    const size_t row1 = row0 + 8 * DD;
    const int cb = 2 * (lane & 3);
#pragma unroll
    for (int j = 0; j < 20; j++) {
        int cc = 8 * j + cb;
        float2 x0 = *(const float2*)(gx + row0 + cc);
        float2 x1 = *(const float2*)(gx + row1 + cc);
        float2 r0v, r1v;
        r0v.x = o[j][0] * inv01 + x0.x;
        r0v.y = o[j][1] * inv01 + x0.y;
        r1v.x = o[j][2] * inv23 + x1.x;
        r1v.y = o[j][3] * inv23 + x1.y;
        *(float2*)(gout + row0 + cc) = r0v;
        *(float2*)(gout + row1 + cc) = r1v;
    }
}

// ---------------------------------------------------------------------------
extern "C" void kernel_launch(void* const* d_in, const int* in_sizes, int n_in,
                              void* d_out, int out_size)
{
    const float* x  = (const float*)d_in[0];
    const float* y  = (const float*)d_in[1];
    const float* Wq = (const float*)d_in[2];
    const float* bq = (const float*)d_in[3];
    const float* Wk = (const float*)d_in[4];
    const float* bk = (const float*)d_in[5];
    const float* Wv = (const float*)d_in[6];
    const float* bv = (const float*)d_in[7];
    float* out = (float*)d_out;

    __half *qh, *ql, *kh, *kl, *vh;
    cudaGetSymbolAddress((void**)&qh, g_qhi);  cudaGetSymbolAddress((void**)&ql, g_qlo);
    cudaGetSymbolAddress((void**)&kh, g_khi);  cudaGetSymbolAddress((void**)&kl, g_klo);
    cudaGetSymbolAddress((void**)&vh, g_vhi);

    cudaFuncSetAttribute(proj_mma,
                         cudaFuncAttributeMaxDynamicSharedMemorySize, PROJ_SMEM);
    dim3 pgrid((B_ * SXX) / BM, 3);   // 512 x 3
    proj_mma<<<pgrid, 256, PROJ_SMEM>>>(x, y, Wq, Wk, Wv,
                                        bq, bk, bv,
                                        qh, ql, kh, kl, vh);

    cudaFuncSetAttribute(attn_kernel,
                         cudaFuncAttributeMaxDynamicSharedMemorySize, SMEM_TOTAL);
    dim3 grid(SXX / BM, B_);
    attn_kernel<<<grid, 256, SMEM_TOTAL>>>(qh, ql, kh, kl, vh, x, out);
}

// round 16
// speedup vs baseline: 1.1558x; 1.1558x over previous
#include <cuda_runtime.h>
#include <cuda_fp16.h>
#include <math.h>
#include <stdint.h>

#define B_    32
#define SXX   2048
#define SYY   2048
#define DD    160
#define BM    128
#define BN    64
#define NT    (SYY / BN)
#define ROWB  336          // padded row pitch in bytes (168 f16)

// hi/lo f16 projections (natural [b][m][d] layout)
__device__ __half g_qhi[(size_t)B_ * SXX * DD];
__device__ __half g_qlo[(size_t)B_ * SXX * DD];
__device__ __half g_khi[(size_t)B_ * SYY * DD];
__device__ __half g_klo[(size_t)B_ * SYY * DD];
__device__ __half g_vhi[(size_t)B_ * SYY * DD];

// ---------------------------------------------------------------------------
// low-level helpers
// ---------------------------------------------------------------------------
__device__ __forceinline__ uint32_t smem_u32(const void* p) {
    uint32_t r;
    asm("{ .reg .u64 t; cvta.to.shared.u64 t, %1; cvt.u32.u64 %0, t; }"
        : "=r"(r) : "l"(p));
    return r;
}
__device__ __forceinline__ void cp16(uint32_t s, const void* g) {
    asm volatile("cp.async.cg.shared.global [%0], [%1], 16;" :: "r"(s), "l"(g));
}
__device__ __forceinline__ void cp_commit() {
    asm volatile("cp.async.commit_group;" ::: "memory");
}
__device__ __forceinline__ void cp_wait_all() {
    asm volatile("cp.async.wait_group 0;" ::: "memory");
}
__device__ __forceinline__ void ldsm4(uint32_t* r, uint32_t a) {
    asm volatile("ldmatrix.sync.aligned.m8n8.x4.shared.b16 {%0,%1,%2,%3}, [%4];"
                 : "=r"(r[0]), "=r"(r[1]), "=r"(r[2]), "=r"(r[3]) : "r"(a));
}
__device__ __forceinline__ void ldsm4t(uint32_t* r, uint32_t a) {
    asm volatile("ldmatrix.sync.aligned.m8n8.x4.trans.shared.b16 {%0,%1,%2,%3}, [%4];"
                 : "=r"(r[0]), "=r"(r[1]), "=r"(r[2]), "=r"(r[3]) : "r"(a));
}
__device__ __forceinline__ void ldsm2t(uint32_t* r, uint32_t a) {
    asm volatile("ldmatrix.sync.aligned.m8n8.x2.trans.shared.b16 {%0,%1}, [%2];"
                 : "=r"(r[0]), "=r"(r[1]) : "r"(a));
}
__device__ __forceinline__ void mma_f16(float* c, const uint32_t* a,
                                        uint32_t b0, uint32_t b1) {
    asm volatile("mma.sync.aligned.m16n8k16.row.col.f32.f16.f16.f32 "
                 "{%0,%1,%2,%3}, {%4,%5,%6,%7}, {%8,%9}, {%0,%1,%2,%3};"
                 : "+f"(c[0]), "+f"(c[1]), "+f"(c[2]), "+f"(c[3])
                 : "r"(a[0]), "r"(a[1]), "r"(a[2]), "r"(a[3]), "r"(b0), "r"(b1));
}
__device__ __forceinline__ float ex2f(float x) {
    float r;
    asm("ex2.approx.ftz.f32 %0, %1;" : "=f"(r) : "f"(x));
    return r;
}
__device__ __forceinline__ uint32_t ex2h2(uint32_t x) {
    uint32_t r;
    asm("ex2.approx.f16x2 %0, %1;" : "=r"(r) : "r"(x));
    return r;
}
__device__ __forceinline__ uint32_t packh(float a, float b) {
    __half2 t = __floats2half2_rn(a, b);
    return *reinterpret_cast<uint32_t*>(&t);
}
// fp32x4 -> hi/lo f16x2 pairs
__device__ __forceinline__ void cvt_hilo(float4 v, uint2& hp, uint2& lp) {
    __half h0 = __float2half_rn(v.x);
    __half h1 = __float2half_rn(v.y);
    __half h2 = __float2half_rn(v.z);
    __half h3 = __float2half_rn(v.w);
    hp.x = ((uint32_t)__half_as_ushort(h1) << 16) | __half_as_ushort(h0);
    hp.y = ((uint32_t)__half_as_ushort(h3) << 16) | __half_as_ushort(h2);
    lp.x = packh(v.x - __half2float(h0), v.y - __half2float(h1));
    lp.y = packh(v.z - __half2float(h2), v.w - __half2float(h3));
}

// ---------------------------------------------------------------------------
// Merged tensor-core projections, fused fp32->f16 hi/lo conversion.
// blockIdx.y == 0: Q = x @ Wq^T  (A tile = x)
// blockIdx.y == 1: K = y @ Wk^T THEN V = y @ Wv^T (A tile = y loaded ONCE;
//                  W region overwritten between the two passes)
// ---------------------------------------------------------------------------
#define PSAH 0
#define PSAL 43008
#define PSWH 86016
#define PSWL 139776
#define PROJ_SMEM 193536

__global__ __launch_bounds__(256, 1) void proj_mma(
    const float* __restrict__ x, const float* __restrict__ y,
    const float* __restrict__ wq, const float* __restrict__ wk,
    const float* __restrict__ wv,
    const float* __restrict__ bq, const float* __restrict__ bk,
    const float* __restrict__ bv,
    __half* __restrict__ qh, __half* __restrict__ ql,
    __half* __restrict__ kh, __half* __restrict__ kl,
    __half* __restrict__ vh)
{
    extern __shared__ char smem[];
    const uint32_t sb = smem_u32(smem);
    const int tid  = threadIdx.x;
    const int lane = tid & 31;
    const int w    = tid >> 5;
    const size_t m0 = (size_t)blockIdx.x * BM;

    const float* Asrc;
    const float* Wsrcs[2];
    const float* biases[2];
    __half* Chis[2];
    __half* Clos[2];
    int npass;
    float ascale;
    if (blockIdx.y == 0) {
        Asrc = x;
        Wsrcs[0] = wq; biases[0] = bq; Chis[0] = qh; Clos[0] = ql;
        Wsrcs[1] = wq; biases[1] = bq; Chis[1] = qh; Clos[1] = ql;  // unused
        npass = 1; ascale = 1.4426950408889634f;   // log2(e)
    } else {
        Asrc = y;
        Wsrcs[0] = wk; biases[0] = bk; Chis[0] = kh; Clos[0] = kl;
        Wsrcs[1] = wv; biases[1] = bv; Chis[1] = vh; Clos[1] = nullptr;
        npass = 2; ascale = 1.0f;
    }

    // ---- load A (128 x 160 fp32) -> convert -> smem hi/lo (once) ----
#pragma unroll
    for (int i = 0; i < 20; i++) {
        int idx = i * 256 + tid;
        int row = idx / 40, c4 = idx % 40;
        float4 v = *(const float4*)(Asrc + (m0 + row) * DD + c4 * 4);
        uint2 hp, lp;
        cvt_hilo(v, hp, lp);
        *(uint2*)(smem + PSAH + row * ROWB + c4 * 8) = hp;
        *(uint2*)(smem + PSAL + row * ROWB + c4 * 8) = lp;
    }

    const uint32_t aOff = (uint32_t)((16 * w + (lane & 15)) * ROWB
                                     + ((lane >> 4) << 4));
    const uint32_t bOff = (uint32_t)(((lane & 7) + ((lane >> 4) << 3)) * ROWB
                                     + (((lane >> 3) & 1) << 4));
    const size_t r0 = m0 + 16 * w + (lane >> 2);
    const int cb = 2 * (lane & 3);

    for (int pass = 0; pass < npass; pass++) {
        if (pass > 0) __syncthreads();   // all reads of previous W done

        // ---- load W (160 x 160 fp32) -> convert -> smem hi/lo ----
        const float* Wsrc = Wsrcs[pass];
#pragma unroll
        for (int i = 0; i < 25; i++) {
            int idx = i * 256 + tid;
            int row = idx / 40, c4 = idx % 40;
            float4 v = *(const float4*)(Wsrc + (size_t)row * DD + c4 * 4);
            uint2 hp, lp;
            cvt_hilo(v, hp, lp);
            *(uint2*)(smem + PSWH + row * ROWB + c4 * 8) = hp;
            *(uint2*)(smem + PSWL + row * ROWB + c4 * 8) = lp;
        }
        __syncthreads();

        float c[20][4];
#pragma unroll
        for (int j = 0; j < 20; j++)
#pragma unroll
            for (int u = 0; u < 4; u++) c[j][u] = 0.f;

#pragma unroll
        for (int ks = 0; ks < 10; ks++) {
            uint32_t ah[4], al[4];
            ldsm4(ah, sb + PSAH + aOff + ks * 32);
            ldsm4(al, sb + PSAL + aOff + ks * 32);
#pragma unroll
            for (int nb = 0; nb < 10; nb++) {
                uint32_t bh[4], bl[4];
                ldsm4(bh, sb + PSWH + bOff + nb * (16 * ROWB) + ks * 32);
                ldsm4(bl, sb + PSWL + bOff + nb * (16 * ROWB) + ks * 32);
                mma_f16(c[2 * nb],     ah, bh[0], bh[1]);
                mma_f16(c[2 * nb + 1], ah, bh[2], bh[3]);
                mma_f16(c[2 * nb],     ah, bl[0], bl[1]);
                mma_f16(c[2 * nb + 1], ah, bl[2], bl[3]);
                mma_f16(c[2 * nb],     al, bh[0], bh[1]);
                mma_f16(c[2 * nb + 1], al, bh[2], bh[3]);
            }
        }

        const float* bias = biases[pass];
        __half* Chi = Chis[pass];
        __half* Clo = Clos[pass];
#pragma unroll
        for (int j = 0; j < 20; j++) {
            int n = 8 * j + cb;
            float2 bvv = *(const float2*)(bias + n);
            float v0 = (c[j][0] + bvv.x) * ascale;
            float v1 = (c[j][1] + bvv.y) * ascale;
            float v2 = (c[j][2] + bvv.x) * ascale;
            float v3 = (c[j][3] + bvv.y) * ascale;
            __half h0 = __float2half_rn(v0);
            __half h1 = __float2half_rn(v1);
            __half h2 = __float2half_rn(v2);
            __half h3 = __float2half_rn(v3);
            *(uint32_t*)(Chi + r0 * DD + n) =
                ((uint32_t)__half_as_ushort(h1) << 16) | __half_as_ushort(h0);
            *(uint32_t*)(Chi + (r0 + 8) * DD + n) =
                ((uint32_t)__half_as_ushort(h3) << 16) | __half_as_ushort(h2);
            if (Clo) {
                *(uint32_t*)(Clo + r0 * DD + n) =
                    packh(v0 - __half2float(h0), v1 - __half2float(h1));
                *(uint32_t*)(Clo + (r0 + 8) * DD + n) =
                    packh(v2 - __half2float(h2), v3 - __half2float(h3));
            }
        }
    }
}

// ---------------------------------------------------------------------------
// f16 HMMA flash attention, BN=64 (EXACTLY R14 — best measured config):
// Q-hi frags in registers; Q-lo permanent in smem; K double-buffered,
// V triple-buffered; S 3-term, PV 1-term + ones-column (l via MMA);
// f16x2 exp, online max w/ rescale-skip, deferred PV.
// SMEM: Qlo @0 (43008) | K bufs @43008/@86016 (each Kh +0, Kl +21504)
//       V bufs @129024/@150528/@172032 (21504 each, ones in pad cols)
// ---------------------------------------------------------------------------
#define SQLO  0
#define KLOFF 21504
#define SMEM_TOTAL 193536

__global__ __launch_bounds__(256, 1) void attn_kernel(
    const __half* __restrict__ qhi, const __half* __restrict__ qlo,
    const __half* __restrict__ khi, const __half* __restrict__ klo,
    const __half* __restrict__ vhi,
    const float* __restrict__ gx, float* __restrict__ gout)
{
    extern __shared__ char smem[];
    const uint32_t sb = smem_u32(smem);
    const int tid  = threadIdx.x;
    const int lane = tid & 31;
    const int w    = tid >> 5;
    const int b    = blockIdx.y;
    const int m0   = blockIdx.x * BM;
    const uint32_t kbuf[2] = { 43008u, 86016u };
    const uint32_t vbuf[3] = { 129024u, 150528u, 172032u };

    // ---- stage Q: lo -> permanent region, hi -> K-buf0 (temporary) ----
    {
        const size_t qrow = ((size_t)b * SXX + m0);
#pragma unroll
        for (int i = 0; i < 20; i++) {
            int idx  = i * 256 + tid;
            int half = idx / 2560;          // 0: hi (temp), 1: lo (permanent)
            int rem  = idx - half * 2560;
            int row  = rem / 20, cc = rem - row * 20;
            cp16(sb + (half ? SQLO : kbuf[0]) + row * ROWB + cc * 16,
                 (half ? qlo : qhi) + (qrow + row) * DD + cc * 8);
        }
    }
    cp_commit();
    cp_wait_all();
    __syncthreads();

    // ---- Q-hi a-frags -> registers (persist); Q-lo stays in smem ----
    const uint32_t qOff = (uint32_t)((16 * w + (lane & 15)) * ROWB
                                     + ((lane >> 4) << 4));
    uint32_t qh_f[10][4];
#pragma unroll
    for (int ks = 0; ks < 10; ks++)
        ldsm4(qh_f[ks], sb + kbuf[0] + qOff + ks * 32);
    __syncthreads();   // Q-hi reads done; K-buf0 now owned by the ring

    // ---- init V pad cols 160-167 of all 3 V buffers: {1,0,...,0} ----
    if (tid < 192) {
        int bufi = tid / 64, row = tid % 64;
        uint4* p = (uint4*)(smem + vbuf[bufi] + row * ROWB + 320);
        *p = make_uint4(0x00003C00u, 0u, 0u, 0u);   // half 1.0 at col 160
    }

    const __half* gk0 = khi + (size_t)b * SYY * DD;
    const __half* gk1 = klo + (size_t)b * SYY * DD;
    const __half* gv  = vhi + (size_t)b * SYY * DD;

    // ---- tile 0 load ----
#pragma unroll
    for (int i = 0; i < 15; i++) {
        int idx = i * 256 + tid;
        int mat = idx / 1280;
        int rem = idx - mat * 1280;
        int row = rem / 20, cc = rem - row * 20;
        const __half* g = (mat == 0) ? gk0 : (mat == 1) ? gk1 : gv;
        uint32_t dst = (mat == 2) ? vbuf[0] : kbuf[0] + mat * KLOFF;
        cp16(sb + dst + row * ROWB + cc * 16, g + (size_t)row * DD + cc * 8);
    }
    cp_commit();
    cp_wait_all();
    __syncthreads();

    const uint32_t kOff = (uint32_t)(((lane & 7) + ((lane >> 4) << 3)) * ROWB
                                     + (((lane >> 3) & 1) << 4));
    const uint32_t vOff = (uint32_t)(((lane & 7) + (((lane >> 3) & 1) << 3)) * ROWB
                                     + ((lane >> 4) << 4));
    const uint32_t vOff2 = (uint32_t)(((lane & 7) + (((lane >> 3) & 1) << 3)) * ROWB);

    float o[21][4];   // blocks 0..19 = O cols 0..159; block 20 = l (col 160)
#pragma unroll
    for (int j = 0; j < 21; j++)
#pragma unroll
        for (int u = 0; u < 4; u++) o[j][u] = 0.f;

    float mh01 = -INFINITY, mh23 = -INFINITY;
    uint32_t pah[4][4];

    for (int t = 0; t < NT; t++) {
        const uint32_t kb  = sb + kbuf[t & 1];
        const uint32_t pvb = sb + vbuf[(t + 2) % 3];   // V(t-1)

        if (t + 1 < NT) {
            const uint32_t nkb = sb + kbuf[(t + 1) & 1];
            const uint32_t nvb = sb + vbuf[(t + 1) % 3];
            const size_t grow = (size_t)(t + 1) * BN;
#pragma unroll
            for (int i = 0; i < 15; i++) {
                int idx = i * 256 + tid;
                int mat = idx / 1280;
                int rem = idx - mat * 1280;
                int row = rem / 20, cc = rem - row * 20;
                const __half* g = (mat == 0) ? gk0 : (mat == 1) ? gk1 : gv;
                uint32_t dst = (mat == 2) ? nvb : nkb + mat * KLOFF;
                cp16(dst + row * ROWB + cc * 16,
                     g + (grow + row) * DD + cc * 8);
            }
            cp_commit();
        }

        // ---- S(t) = Q K^T : 3-term f16 hi/lo; Q-lo frags from smem ----
        float c[8][4];
#pragma unroll
        for (int j = 0; j < 8; j++)
#pragma unroll
            for (int u = 0; u < 4; u++) c[j][u] = 0.f;

#pragma unroll
        for (int ks = 0; ks < 10; ks++) {
            uint32_t qlf[4];
            ldsm4(qlf, sb + SQLO + qOff + ks * 32);
#pragma unroll
            for (int nh = 0; nh < 2; nh++) {
                uint32_t bh[8], bl[8];
                uint32_t kbb = kb + kOff + nh * (32 * ROWB) + ks * 32;
                ldsm4(bh,     kbb);
                ldsm4(bh + 4, kbb + 16 * ROWB);
                ldsm4(bl,     kbb + KLOFF);
                ldsm4(bl + 4, kbb + KLOFF + 16 * ROWB);
#pragma unroll
                for (int j = 0; j < 4; j++) {
                    float* cj = c[4 * nh + j];
                    mma_f16(cj, qh_f[ks], bh[2 * j], bh[2 * j + 1]);
                    mma_f16(cj, qh_f[ks], bl[2 * j], bl[2 * j + 1]);
                    mma_f16(cj, qlf,      bh[2 * j], bh[2 * j + 1]);
                }
            }
        }

        // ---- PV(t-1): 1-term (ph*vh) + ones column, k = 64 ----
        if (t > 0) {
#pragma unroll
            for (int ks = 0; ks < 4; ks++) {
#pragma unroll
                for (int jp = 0; jp < 10; jp++) {
                    uint32_t v4h[4];
                    ldsm4t(v4h, pvb + vOff + ks * (16 * ROWB) + jp * 32);
                    mma_f16(o[2 * jp],     pah[ks], v4h[0], v4h[1]);
                    mma_f16(o[2 * jp + 1], pah[ks], v4h[2], v4h[3]);
                }
                uint32_t v2[2];
                ldsm2t(v2, pvb + vOff2 + ks * (16 * ROWB) + 320);
                mma_f16(o[20], pah[ks], v2[0], v2[1]);
            }
        }

        // ---- online softmax(t): scores in log2 units; exp in f16x2 ----
        float mt01 = fmaxf(c[0][0], c[0][1]);
        float mt23 = fmaxf(c[0][2], c[0][3]);
#pragma unroll
        for (int j = 1; j < 8; j++) {
            mt01 = fmaxf(mt01, fmaxf(c[j][0], c[j][1]));
            mt23 = fmaxf(mt23, fmaxf(c[j][2], c[j][3]));
        }
        mt01 = fmaxf(mt01, __shfl_xor_sync(0xffffffffu, mt01, 1));
        mt01 = fmaxf(mt01, __shfl_xor_sync(0xffffffffu, mt01, 2));
        mt23 = fmaxf(mt23, __shfl_xor_sync(0xffffffffu, mt23, 1));
        mt23 = fmaxf(mt23, __shfl_xor_sync(0xffffffffu, mt23, 2));
        const bool upd = (mt01 > mh01) || (mt23 > mh23);
        float mn01 = fmaxf(mh01, mt01);
        float mn23 = fmaxf(mh23, mt23);
        float a01 = ex2f(mh01 - mn01);
        float a23 = ex2f(mh23 - mn23);
        mh01 = mn01; mh23 = mn23;

#pragma unroll
        for (int j = 0; j < 8; j++) {
            float t0 = c[j][0] - mn01;
            float t1 = c[j][1] - mn01;
            float t2 = c[j][2] - mn23;
            float t3 = c[j][3] - mn23;
            int ks = j >> 1, sl = (j & 1) << 1;
            pah[ks][sl]     = ex2h2(packh(t0, t1));
            pah[ks][sl + 1] = ex2h2(packh(t2, t3));
        }

        if (upd) {   // rescale O (incl. l column) only when max advanced
#pragma unroll
            for (int j = 0; j < 21; j++) {
                o[j][0] *= a01; o[j][1] *= a01;
                o[j][2] *= a23; o[j][3] *= a23;
            }
        }

        cp_wait_all();
        __syncthreads();
    }

    // ---- final PV (tile NT-1) ----
    {
        const uint32_t pvb = sb + vbuf[(NT - 1) % 3];
#pragma unroll
        for (int ks = 0; ks < 4; ks++) {
#pragma unroll
            for (int jp = 0; jp < 10; jp++) {
                uint32_t v4h[4];
                ldsm4t(v4h, pvb + vOff + ks * (16 * ROWB) + jp * 32);
                mma_f16(o[2 * jp],     pah[ks], v4h[0], v4h[1]);
                mma_f16(o[2 * jp + 1], pah[ks], v4h[2], v4h[3]);
            }
            uint32_t v2[2];
            ldsm2t(v2, pvb + vOff2 + ks * (16 * ROWB) + 320);
            mma_f16(o[20], pah[ks], v2[0], v2[1]);
        }
    }

    // ---- epilogue: l = O col 160 (held by lanes with lane&3 == 0) ----
    const int srcl = lane & ~3;
    const float l01 = __shfl_sync(0xffffffffu, o[20][0], srcl);
    const float l23 = __shfl_sync(0xffffffffu, o[20][2], srcl);
    const float inv01 = 1.f / l01;
    const float inv23 = 1.f / l23;

    const int r0 = m0 + 16 * w + (lane >> 2);
    const size_t row0 = ((size_t)b * SXX + r0) * DD;
    const size_t row1 = row0 + 8 * DD;
    const int cb = 2 * (lane & 3);
#pragma unroll
    for (int j = 0; j < 20; j++) {
        int cc = 8 * j + cb;
        float2 x0 = *(const float2*)(gx + row0 + cc);
        float2 x1 = *(const float2*)(gx + row1 + cc);
        float2 r0v, r1v;
        r0v.x = o[j][0] * inv01 + x0.x;
        r0v.y = o[j][1] * inv01 + x0.y;
        r1v.x = o[j][2] * inv23 + x1.x;
        r1v.y = o[j][3] * inv23 + x1.y;
        *(float2*)(gout + row0 + cc) = r0v;
        *(float2*)(gout + row1 + cc) = r1v;
    }
}

// ---------------------------------------------------------------------------
extern "C" void kernel_launch(void* const* d_in, const int* in_sizes, int n_in,
                              void* d_out, int out_size)
{
    const float* x  = (const float*)d_in[0];
    const float* y  = (const float*)d_in[1];
    const float* Wq = (const float*)d_in[2];
    const float* bq = (const float*)d_in[3];
    const float* Wk = (const float*)d_in[4];
    const float* bk = (const float*)d_in[5];
    const float* Wv = (const float*)d_in[6];
    const float* bv = (const float*)d_in[7];
    float* out = (float*)d_out;

    __half *qh, *ql, *kh, *kl, *vh;
    cudaGetSymbolAddress((void**)&qh, g_qhi);  cudaGetSymbolAddress((void**)&ql, g_qlo);
    cudaGetSymbolAddress((void**)&kh, g_khi);  cudaGetSymbolAddress((void**)&kl, g_klo);
    cudaGetSymbolAddress((void**)&vh, g_vhi);

    cudaFuncSetAttribute(proj_mma,
                         cudaFuncAttributeMaxDynamicSharedMemorySize, PROJ_SMEM);
    dim3 pgrid((B_ * SXX) / BM, 2);   // 512 x 2: y=0 -> Q, y=1 -> K then V
    proj_mma<<<pgrid, 256, PROJ_SMEM>>>(x, y, Wq, Wk, Wv,
                                        bq, bk, bv,
                                        qh, ql, kh, kl, vh);

    cudaFuncSetAttribute(attn_kernel,
                         cudaFuncAttributeMaxDynamicSharedMemorySize, SMEM_TOTAL);
    dim3 grid(SXX / BM, B_);
    attn_kernel<<<grid, 256, SMEM_TOTAL>>>(qh, ql, kh, kl, vh, x, out);
}